// round 10
// baseline (speedup 1.0000x reference)
#include <cuda_runtime.h>

// SplineLoss on GB300: reference samples the spline only at integer knot
// times (t = 0,10,...,1020) where dx == 0.0 exactly, so all moment terms
// vanish: loss == mean over s,b,d of (true[b,10s,d]-pred[b,10s,d])^2.
//
// R10 = R7 structure (824x256 single wave, 8-bin two-level atomic tail)
// with the SHFL reduction trees replaced by integer redux.sync.add.u32
// (f32 redux doesn't exist on sm_103; integer does). Per-thread fixed-point
// quantization at 2^21: exact commutative integer adds -> deterministic;
// quantization rel err ~6e-6 << 1e-3 tolerance.

#define T_ 1024
#define D4_ 16                   // 64 floats per row = 16 float4
#define S_ 103                   // sample times 0,10,...,1020
#define ROW_STRIDE4_ (T_ * D4_)  // float4 stride between batches
#define COUNT_ 843776.0          // 128 * 103 * 64
#define FIX_SCALE 2097152.0     // 2^21

constexpr int NBLK  = 8 * S_;    // 824 blocks, 8 per sample time
constexpr int NTHR  = 256;       // 16 batches x 16 float4
constexpr int NBINS = 8;
constexpr int BINSZ = NBLK / NBINS;   // 103

__device__ __align__(256) unsigned long long g_bins[NBINS * 32]; // use [i*32]
__device__ __align__(256) unsigned long long g_final = 0;

__device__ __forceinline__ unsigned warp_redux_add_u32(unsigned x) {
    unsigned r;
    asm volatile("redux.sync.add.u32 %0, %1, 0xffffffff;"
                 : "=r"(r) : "r"(x));
    return r;
}

__global__ __launch_bounds__(NTHR) void spline_mse_r10(
    const float* __restrict__ yt, const float* __restrict__ yp,
    float* __restrict__ out)
{
    const int s = blockIdx.x >> 3;             // 0..102
    const int q = blockIdx.x & 7;              // batch group [16q, 16q+16)
    const int d4   = threadIdx.x & (D4_ - 1);
    const int brel = threadIdx.x >> 4;         // 0..15

    const int addr = s * 10 * D4_ + (q * 16 + brel) * ROW_STRIDE4_ + d4;
    const float4 va = __ldg((const float4*)yt + addr);
    const float4 vb = __ldg((const float4*)yp + addr);

    float e0 = va.x - vb.x;
    float e1 = va.y - vb.y;
    float e2 = va.z - vb.z;
    float e3 = va.w - vb.w;
    float acc = e0 * e0;
    acc = fmaf(e1, e1, acc);
    acc = fmaf(e2, e2, acc);
    acc = fmaf(e3, e3, acc);

    // per-thread fixed-point quantization (deterministic, rel err ~6e-6)
    unsigned fx = __float2uint_rn(acc * (float)FIX_SCALE);

    // warp reduce: one instruction (integer, exact)
    fx = warp_redux_add_u32(fx);

    __shared__ unsigned sh[NTHR / 32];
    if ((threadIdx.x & 31) == 0) sh[threadIdx.x >> 5] = fx;
    __syncthreads();

    if (threadIdx.x >= 32) return;             // warp 0 only

    unsigned v = (threadIdx.x < NTHR / 32) ? sh[threadIdx.x] : 0u;
    v = warp_redux_add_u32(v);

    if (threadIdx.x != 0) return;

    // level 1: bin atomic (103 blocks per address, 8 addresses in parallel)
    unsigned long long fixed = (unsigned long long)v;    // exact block sum
    unsigned long long* bin = &g_bins[(blockIdx.x & (NBINS - 1)) * 32];
    unsigned long long old = atomicAdd(bin, (fixed << 16) | 1ull);

    if ((old & 0xFFFFull) != (unsigned long long)(BINSZ - 1)) return;

    // bin-last: forward exact bin total, reset bin for next replay
    unsigned long long bin_total = (old >> 16) + fixed;
    *bin = 0ull;                                         // no later readers
    unsigned long long fold = atomicAdd(&g_final, (bin_total << 16) | 1ull);

    if ((fold & 0xFFFFull) == (unsigned long long)(NBINS - 1)) {
        unsigned long long total = (fold >> 16) + bin_total;
        out[0] = (float)((double)total / (FIX_SCALE * COUNT_));
        g_final = 0ull;                                  // reset for replay
    }
}

extern "C" void kernel_launch(void* const* d_in, const int* in_sizes, int n_in,
                              void* d_out, int out_size)
{
    const float* yt = (const float*)d_in[0];   // true_frames
    const float* yp = (const float*)d_in[1];   // predicted_frames
    spline_mse_r10<<<NBLK, NTHR>>>(yt, yp, (float*)d_out);
}